// round 3
// baseline (speedup 1.0000x reference)
#include <cuda_runtime.h>

// AtteMatchLay: multi-perspective cosine similarity.
// out[n][p] = dot / (max(sqrt(n1),eps) * max(sqrt(n2),eps))
//   dot = sum_d r[n][d]*m[n][d]*w2[p][d]
//   n1  = sum_d r^2 * w2,  n2 = sum_d m^2 * w2,  w2 = weight^2
// N = 8192 rows, D = 768, P = 20. fp32 in/out.
//
// Design: warp = 4 rows x 8 d-lanes. w^2 staged transposed [D][P] in shared
// (stride 20 floats = 80B: 16B-aligned for LDS.128, bank-conflict-free for
// the 80B lane stride). Accumulators packed as f32x2 over p-pairs, driven
// by fma.rn.f32x2 (FFMA2 = 2x fp32 rate on sm_103a, PTX-only).

#define DD 768
#define PP 20
#define WSTRIDE 20  // floats per d-row of w2t in shared

typedef unsigned long long u64;

__device__ __forceinline__ u64 pack2(float x) {
    u64 r;
    asm("mov.b64 %0, {%1, %1};" : "=l"(r) : "f"(x));
    return r;
}
__device__ __forceinline__ float2 unpack2(u64 v) {
    float2 f;
    asm("mov.b64 {%0, %1}, %2;" : "=f"(f.x), "=f"(f.y) : "l"(v));
    return f;
}
__device__ __forceinline__ void fma2(u64& d, u64 a, u64 b) {
    asm("fma.rn.f32x2 %0, %1, %2, %0;" : "+l"(d) : "l"(a), "l"(b));
}

extern "C" __global__ void __launch_bounds__(256, 2)
atte_matchlay_kernel(const float* __restrict__ repres,
                     const float* __restrict__ max_att,
                     const float* __restrict__ weight,
                     float* __restrict__ out, int nrows)
{
    extern __shared__ float w2t[];  // [DD][WSTRIDE]

    // Stage w^2 transposed: w2t[d][p] = weight[p][d]^2
    for (int idx = threadIdx.x; idx < PP * DD; idx += blockDim.x) {
        int p = idx / DD;
        int d = idx - p * DD;
        float w = weight[idx];
        w2t[d * WSTRIDE + p] = w * w;
    }
    __syncthreads();

    const int warp = threadIdx.x >> 5;
    const int lane = threadIdx.x & 31;
    const int rg   = lane >> 3;   // row within warp (0..3)
    const int dl   = lane & 7;    // d-lane (0..7)
    const int row  = (blockIdx.x * 8 + warp) * 4 + rg;
    if (row >= nrows) return;

    const float4* __restrict__ rptr = (const float4*)(repres + (size_t)row * DD);
    const float4* __restrict__ mptr = (const float4*)(max_att + (size_t)row * DD);

    u64 acc_dot[10], acc_n1[10], acc_n2[10];
#pragma unroll
    for (int k = 0; k < 10; k++) {
        acc_dot[k] = 0ull; acc_n1[k] = 0ull; acc_n2[k] = 0ull;
    }

    // Each vec-iter: this lane handles 4 consecutive d at d0 = i*32 + dl*4.
    // 24 iters cover D=768 (8 d-lanes x 4 floats x 24 = 768).
    float4 r4 = rptr[dl];
    float4 m4 = mptr[dl];

#pragma unroll 2
    for (int i = 0; i < 24; i++) {
        // prefetch next (clamped; re-reads last tile harmlessly)
        int nx = (i < 23) ? (i + 1) : 23;
        float4 rn = rptr[nx * 8 + dl];
        float4 mn = mptr[nx * 8 + dl];

        const int d0 = i * 32 + dl * 4;
        float rv[4] = {r4.x, r4.y, r4.z, r4.w};
        float mv[4] = {m4.x, m4.y, m4.z, m4.w};

#pragma unroll
        for (int j = 0; j < 4; j++) {
            const int d = d0 + j;
            const ulonglong2* wp = (const ulonglong2*)(w2t + d * WSTRIDE);
            ulonglong2 wA = wp[0];  // p0..3  (two f32x2 pairs)
            ulonglong2 wB = wp[1];  // p4..7
            ulonglong2 wC = wp[2];  // p8..11
            ulonglong2 wD = wp[3];  // p12..15
            ulonglong2 wE = wp[4];  // p16..19
            u64 wv[10] = {wA.x, wA.y, wB.x, wB.y, wC.x, wC.y,
                          wD.x, wD.y, wE.x, wE.y};

            float r = rv[j], m = mv[j];
            u64 rm = pack2(r * m);
            u64 rr = pack2(r * r);
            u64 mm = pack2(m * m);

#pragma unroll
            for (int k = 0; k < 10; k++) {
                fma2(acc_dot[k], rm, wv[k]);
                fma2(acc_n1[k],  rr, wv[k]);
                fma2(acc_n2[k],  mm, wv[k]);
            }
        }
        r4 = rn; m4 = mn;
    }

    // Unpack to 60 floats
    float dot[PP], n1[PP], n2[PP];
#pragma unroll
    for (int k = 0; k < 10; k++) {
        float2 a = unpack2(acc_dot[k]); dot[2*k] = a.x; dot[2*k+1] = a.y;
        float2 b = unpack2(acc_n1[k]);  n1[2*k]  = b.x; n1[2*k+1]  = b.y;
        float2 c = unpack2(acc_n2[k]);  n2[2*k]  = c.x; n2[2*k+1]  = c.y;
    }

    // Reduce across the 8 d-lanes of this row (xor within low 3 bits of lane)
#pragma unroll
    for (int p = 0; p < PP; p++) {
#pragma unroll
        for (int o = 1; o < 8; o <<= 1) {
            dot[p] += __shfl_xor_sync(0xffffffffu, dot[p], o);
            n1[p]  += __shfl_xor_sync(0xffffffffu, n1[p],  o);
            n2[p]  += __shfl_xor_sync(0xffffffffu, n2[p],  o);
        }
    }

    // All 8 lanes of the group hold full sums; each writes ~3 outputs.
    const float EPS = 1e-8f;
#pragma unroll
    for (int p0 = 0; p0 < PP; p0 += 8) {
        int p = p0 + dl;
        if (p < PP) {
            float a = fmaxf(sqrtf(n1[p]), EPS);
            float b = fmaxf(sqrtf(n2[p]), EPS);
            out[(size_t)row * PP + p] = dot[p] / (a * b);
        }
    }
}

extern "C" void kernel_launch(void* const* d_in, const int* in_sizes, int n_in,
                              void* d_out, int out_size) {
    const float* repres  = (const float*)d_in[0];
    const float* max_att = (const float*)d_in[1];
    const float* weight  = (const float*)d_in[2];
    float* out = (float*)d_out;

    int nrows = in_sizes[0] / DD;              // 8192
    int smem  = DD * WSTRIDE * sizeof(float);  // 61440 B

    cudaFuncSetAttribute(atte_matchlay_kernel,
                         cudaFuncAttributeMaxDynamicSharedMemorySize, smem);

    int rows_per_block = 32;                   // 8 warps x 4 rows
    int grid = (nrows + rows_per_block - 1) / rows_per_block;
    atte_matchlay_kernel<<<grid, 256, smem>>>(repres, max_att, weight, out, nrows);
}

// round 7
// speedup vs baseline: 2.3577x; 2.3577x over previous
#include <cuda_runtime.h>

// AtteMatchLay: multi-perspective cosine similarity.
// out[n][p] = dot / (max(sqrt(n1),eps) * max(sqrt(n2),eps))
//   dot = sum_d r[n][d]*m[n][d]*w2[p][d]
//   n1  = sum_d r^2 * w2,  n2 = sum_d m^2 * w2,  w2 = weight^2
// N = 8192 rows, D = 768, P = 20. fp32 in/out.
//
// Warp = 4 rows x 8 d-lanes. w^2 staged transposed [D][P] in shared, with a
// BLOCK-LOCAL swizzle (R3's global swizzle was non-injective at the 32-row
// wrap and corrupted w^2):
//   block b = d>>5 gets a fixed 2688B slot; within it, local row d'=d&31 at
//   d'*80 + ((d'>>2))*16.  (d'>>2) is monotone within a block -> injective.
// All 8 lanes of a warp load share the same block (d = i*32 + 4*dl + j), so
// per-load word offsets are 84*dl + const == {0,20,8,28,16,4,24,12} mod 32:
// eight distinct 16B reads tiling all 32 banks -> ZERO conflicts (R0 had
// 4-way conflicts -> L1 71.7% bound). 16B alignment preserved.
// Accumulators packed as f32x2 over p-pairs via fma.rn.f32x2 (2x fp32 rate).

#define DD 768
#define PP 20
#define BLKB 2688   // bytes per 32-d block (32*80 + 7*16 + pad, 16B aligned)

typedef unsigned long long u64;

__device__ __forceinline__ int w2t_off(int d) {
    int b = d >> 5;
    int dl = d & 31;
    return b * BLKB + dl * 80 + ((dl >> 2) & 7) * 16;
}

__device__ __forceinline__ u64 pack2(float x) {
    u64 r;
    asm("mov.b64 %0, {%1, %1};" : "=l"(r) : "f"(x));
    return r;
}
__device__ __forceinline__ float2 unpack2(u64 v) {
    float2 f;
    asm("mov.b64 {%0, %1}, %2;" : "=f"(f.x), "=f"(f.y) : "l"(v));
    return f;
}
__device__ __forceinline__ void fma2(u64& d, u64 a, u64 b) {
    asm("fma.rn.f32x2 %0, %1, %2, %0;" : "+l"(d) : "l"(a), "l"(b));
}

extern "C" __global__ void __launch_bounds__(256, 2)
atte_matchlay_kernel(const float* __restrict__ repres,
                     const float* __restrict__ max_att,
                     const float* __restrict__ weight,
                     float* __restrict__ out, int nrows)
{
    extern __shared__ char w2t[];  // swizzled [DD][PP] fp32, 64512 B

    // Stage w^2 transposed+swizzled: w2t[off(d) + 4p] = weight[p][d]^2
    for (int idx = threadIdx.x; idx < PP * DD; idx += blockDim.x) {
        int p = idx / DD;
        int d = idx - p * DD;
        float w = weight[idx];
        *(float*)(w2t + w2t_off(d) + p * 4) = w * w;
    }
    __syncthreads();

    const int warp = threadIdx.x >> 5;
    const int lane = threadIdx.x & 31;
    const int rg   = lane >> 3;   // row within warp (0..3)
    const int dl   = lane & 7;    // d-lane (0..7)
    const int row  = (blockIdx.x * 8 + warp) * 4 + rg;
    if (row >= nrows) return;

    const float4* __restrict__ rptr = (const float4*)(repres + (size_t)row * DD);
    const float4* __restrict__ mptr = (const float4*)(max_att + (size_t)row * DD);

    u64 acc_dot[10], acc_n1[10], acc_n2[10];
#pragma unroll
    for (int k = 0; k < 10; k++) {
        acc_dot[k] = 0ull; acc_n1[k] = 0ull; acc_n2[k] = 0ull;
    }

    // Each vec-iter: this lane handles 4 consecutive d at d0 = i*32 + dl*4.
    // 24 iters cover D=768 (8 d-lanes x 4 floats x 24 = 768).
    float4 r4 = rptr[dl];
    float4 m4 = mptr[dl];

#pragma unroll 2
    for (int i = 0; i < 24; i++) {
        // prefetch next (clamped; re-reads last tile harmlessly)
        int nx = (i < 23) ? (i + 1) : 23;
        float4 rn = rptr[nx * 8 + dl];
        float4 mn = mptr[nx * 8 + dl];

        const int d0 = i * 32 + dl * 4;
        float rv[4] = {r4.x, r4.y, r4.z, r4.w};
        float mv[4] = {m4.x, m4.y, m4.z, m4.w};

#pragma unroll
        for (int j = 0; j < 4; j++) {
            const int d = d0 + j;
            const ulonglong2* wp = (const ulonglong2*)(w2t + w2t_off(d));
            ulonglong2 wA = wp[0];  // p0..3  (two f32x2 pairs)
            ulonglong2 wB = wp[1];  // p4..7
            ulonglong2 wC = wp[2];  // p8..11
            ulonglong2 wD = wp[3];  // p12..15
            ulonglong2 wE = wp[4];  // p16..19
            u64 wv[10] = {wA.x, wA.y, wB.x, wB.y, wC.x, wC.y,
                          wD.x, wD.y, wE.x, wE.y};

            float r = rv[j], m = mv[j];
            u64 rm = pack2(r * m);
            u64 rr = pack2(r * r);
            u64 mm = pack2(m * m);

#pragma unroll
            for (int k = 0; k < 10; k++) {
                fma2(acc_dot[k], rm, wv[k]);
                fma2(acc_n1[k],  rr, wv[k]);
                fma2(acc_n2[k],  mm, wv[k]);
            }
        }
        r4 = rn; m4 = mn;
    }

    // Unpack to 60 floats
    float dot[PP], n1[PP], n2[PP];
#pragma unroll
    for (int k = 0; k < 10; k++) {
        float2 a = unpack2(acc_dot[k]); dot[2*k] = a.x; dot[2*k+1] = a.y;
        float2 b = unpack2(acc_n1[k]);  n1[2*k]  = b.x; n1[2*k+1]  = b.y;
        float2 c = unpack2(acc_n2[k]);  n2[2*k]  = c.x; n2[2*k+1]  = c.y;
    }

    // Reduce across the 8 d-lanes of this row (xor within low 3 bits of lane)
#pragma unroll
    for (int p = 0; p < PP; p++) {
#pragma unroll
        for (int o = 1; o < 8; o <<= 1) {
            dot[p] += __shfl_xor_sync(0xffffffffu, dot[p], o);
            n1[p]  += __shfl_xor_sync(0xffffffffu, n1[p],  o);
            n2[p]  += __shfl_xor_sync(0xffffffffu, n2[p],  o);
        }
    }

    // All 8 lanes of the group hold full sums; each writes ~3 outputs.
    const float EPS = 1e-8f;
#pragma unroll
    for (int p0 = 0; p0 < PP; p0 += 8) {
        int p = p0 + dl;
        if (p < PP) {
            float a = fmaxf(sqrtf(n1[p]), EPS);
            float b = fmaxf(sqrtf(n2[p]), EPS);
            out[(size_t)row * PP + p] = dot[p] / (a * b);
        }
    }
}

extern "C" void kernel_launch(void* const* d_in, const int* in_sizes, int n_in,
                              void* d_out, int out_size) {
    const float* repres  = (const float*)d_in[0];
    const float* max_att = (const float*)d_in[1];
    const float* weight  = (const float*)d_in[2];
    float* out = (float*)d_out;

    int nrows = in_sizes[0] / DD;                 // 8192
    int smem  = (DD / 32) * BLKB;                 // 24 * 2688 = 64512 B

    cudaFuncSetAttribute(atte_matchlay_kernel,
                         cudaFuncAttributeMaxDynamicSharedMemorySize, smem);

    int rows_per_block = 32;                      // 8 warps x 4 rows
    int grid = (nrows + rows_per_block - 1) / rows_per_block;
    atte_matchlay_kernel<<<grid, 256, smem>>>(repres, max_att, weight, out, nrows);
}